// round 15
// baseline (speedup 1.0000x reference)
#include <cuda_runtime.h>
#include <cuda_bf16.h>
#include <cstdint>

#define H 256
#define P_PATHS 32768
#define LMAX 16
#define NKS 18                 // k-steps of 16 (K = 288)
#define MTILE 64               // paths per tile
#define NT (P_PATHS / MTILE)   // 512 tiles
#define GRID 148
#define THREADS 768            // 16 consumer warps + 8 producer warps

// ---- dynamic smem byte offsets ----
#define ASTRB 592              // A row stride bytes (odd 16B segs -> conflict-free ldsm)
#define BSTRB 528
#define AHL   37888            // hi (or lo) plane: 64*592
#define ABUF  75776            // one A buffer = hi + lo
#define OFF_B  151552
#define BBUF   16896           // one B buffer (hi 8448 + lo 8448)
#define BSPL   8448
#define OFF_CS 185344
#define OFF_W2 186368
#define OFF_QP 187392          // float[64][17]
#define OFF_TK 191744          // int[2]
#define SMEM_BYTES 191760

// ---------------- persistent scratch ----------------
__device__ __align__(128) unsigned g_Bh[NKS * 2048];   // [chunk][k(16)][n2(128)] bf16x2
__device__ __align__(128) unsigned g_Bl[NKS * 2048];
__device__ __align__(128) float g_cpart[8][H];
__device__ int g_ticket;

// ---------------- helpers ----------------
__device__ __forceinline__ uint32_t smem_u32(const void* p) {
    uint32_t a;
    asm("{ .reg .u64 t; cvta.to.shared.u64 t, %1; cvt.u32.u64 %0, t; }" : "=r"(a) : "l"(p));
    return a;
}
__device__ __forceinline__ void split2(float a, float b, unsigned& h, unsigned& l) {
    __nv_bfloat16 ha = __float2bfloat16_rn(a), hb = __float2bfloat16_rn(b);
    float ra = a - __bfloat162float(ha), rb = b - __bfloat162float(hb);
    __nv_bfloat16 la = __float2bfloat16_rn(ra), lb = __float2bfloat16_rn(rb);
    h = (unsigned)__bfloat16_as_ushort(ha) | ((unsigned)__bfloat16_as_ushort(hb) << 16);
    l = (unsigned)__bfloat16_as_ushort(la) | ((unsigned)__bfloat16_as_ushort(lb) << 16);
}
__device__ __forceinline__ void ldsm4(unsigned* r, uint32_t a) {
    asm volatile("ldmatrix.sync.aligned.m8n8.x4.shared.b16 {%0,%1,%2,%3}, [%4];"
                 : "=r"(r[0]), "=r"(r[1]), "=r"(r[2]), "=r"(r[3]) : "r"(a));
}
__device__ __forceinline__ void ldsm4t(unsigned* r, uint32_t a) {
    asm volatile("ldmatrix.sync.aligned.m8n8.x4.trans.shared.b16 {%0,%1,%2,%3}, [%4];"
                 : "=r"(r[0]), "=r"(r[1]), "=r"(r[2]), "=r"(r[3]) : "r"(a));
}
__device__ __forceinline__ void mma_bf16(float* d, const unsigned* a, unsigned b0, unsigned b1) {
    asm volatile("mma.sync.aligned.m16n8k16.row.col.f32.bf16.bf16.f32 "
                 "{%0,%1,%2,%3}, {%4,%5,%6,%7}, {%8,%9}, {%0,%1,%2,%3};"
                 : "+f"(d[0]), "+f"(d[1]), "+f"(d[2]), "+f"(d[3])
                 : "r"(a[0]), "r"(a[1]), "r"(a[2]), "r"(a[3]), "r"(b0), "r"(b1));
}
__device__ __forceinline__ void cpa16(uint32_t dst, const void* src) {
    asm volatile("cp.async.cg.shared.global [%0], [%1], 16;" :: "r"(dst), "l"(src) : "memory");
}
#define CPA_COMMIT asm volatile("cp.async.commit_group;" ::: "memory")
#define CPA_WAIT1  asm volatile("cp.async.wait_group 1;"  ::: "memory")
#define BARC()     asm volatile("bar.sync 1, 512;" ::: "memory")   // consumers only

// fused-k -> W1 row: [src 0:256 | dst 256:512 | emb 512:768 | edge 768:776 | scalar 776:792]
__device__ __forceinline__ float wfused(const float* W1, int kg, int j) {
    if (kg < 256) return W1[(512 + kg) * H + j];
    if (kg < 264) return W1[(768 + (kg - 256)) * H + j];
    if (kg < 280) return W1[(776 + (kg - 264)) * H + j];
    return 0.f;
}

// ---------------- kernel 1: prep ----------------
__global__ void prep_kernel(const float* __restrict__ W1,
                            const float* __restrict__ node_embs,
                            const float* __restrict__ b1,
                            const int* __restrict__ src_idx,
                            const int* __restrict__ dst_idx) {
    int bid = blockIdx.x;
    int t = threadIdx.x;
    if (bid == 0 && t == 0) g_ticket = GRID;
    if (bid < NKS) {
        int c = bid;
        int kk = t >> 7;
        int n2 = t & 127;
#pragma unroll
        for (int i = 0; i < 8; i++) {
            int k = i * 2 + kk;
            float v0 = wfused(W1, c * 16 + k, 2 * n2);
            float v1 = wfused(W1, c * 16 + k, 2 * n2 + 1);
            unsigned hp, lp; split2(v0, v1, hp, lp);
            int idx = c * 2048 + k * 128 + n2;
            g_Bh[idx] = hp;
            g_Bl[idx] = lp;
        }
    } else {
        int b = bid - NKS;
        const float* s = node_embs + (long)(*src_idx) * H;
        const float* d = node_embs + (long)(*dst_idx) * H;
        float acc = (b == 0) ? b1[t] : 0.f;
        int k0 = b * 32;
#pragma unroll 8
        for (int k = k0; k < k0 + 32; k++) {
            acc = fmaf(s[k], W1[k * H + t], acc);
            acc = fmaf(d[k], W1[(256 + k) * H + t], acc);
        }
        g_cpart[b][t] = acc;
    }
}

// ---------------- gather: one path mean -> bf16 hi/lo rows of A ----------------
__device__ __forceinline__ void gather_path(char* __restrict__ Ah, char* __restrict__ Al,
                                            const float* __restrict__ node_embs,
                                            const int* __restrict__ path_nodes,
                                            const int* __restrict__ path_lens,
                                            int p, int pl, int lane) {
    int len = path_lens[p];
    const int4* nb = (const int4*)(path_nodes + (size_t)p * LMAX);
    int4 q0 = nb[0], q1 = nb[1], q2 = nb[2], q3 = nb[3];
    int ids[16] = {q0.x, q0.y, q0.z, q0.w, q1.x, q1.y, q1.z, q1.w,
                   q2.x, q2.y, q2.z, q2.w, q3.x, q3.y, q3.z, q3.w};
    float4 a0 = make_float4(0.f, 0.f, 0.f, 0.f);
    float4 a1 = make_float4(0.f, 0.f, 0.f, 0.f);
#pragma unroll
    for (int l = 0; l < LMAX; l++) {
        if (l < len) {
            const float4* r = (const float4*)(node_embs + (size_t)ids[l] * H);
            float4 v0 = r[lane];
            float4 v1 = r[32 + lane];
            a0.x += v0.x; a0.y += v0.y; a0.z += v0.z; a0.w += v0.w;
            a1.x += v1.x; a1.y += v1.y; a1.z += v1.z; a1.w += v1.w;
        }
    }
    float inv = 1.f / (float)max(len, 1);
    unsigned h01, l01, h23, l23;
    split2(a0.x * inv, a0.y * inv, h01, l01);
    split2(a0.z * inv, a0.w * inv, h23, l23);
    *(uint2*)(Ah + pl * ASTRB + lane * 8) = make_uint2(h01, h23);
    *(uint2*)(Al + pl * ASTRB + lane * 8) = make_uint2(l01, l23);
    split2(a1.x * inv, a1.y * inv, h01, l01);
    split2(a1.z * inv, a1.w * inv, h23, l23);
    *(uint2*)(Ah + pl * ASTRB + 256 + lane * 8) = make_uint2(h01, h23);
    *(uint2*)(Al + pl * ASTRB + 256 + lane * 8) = make_uint2(l01, l23);
}

__device__ __forceinline__ void feat_rows(char* __restrict__ Ah, char* __restrict__ Al,
                                          const float* __restrict__ edge_feats,
                                          const float* __restrict__ scalar_feats,
                                          int p, int pl) {
    const float4* ef = (const float4*)(edge_feats + (size_t)p * 8);
    float4 e0 = ef[0], e1 = ef[1];
    const float4* sf = (const float4*)(scalar_feats + (size_t)p * 16);
    float4 s0 = sf[0], s1 = sf[1], s2 = sf[2], s3 = sf[3];
    float v[24] = {e0.x, e0.y, e0.z, e0.w, e1.x, e1.y, e1.z, e1.w,
                   s0.x, s0.y, s0.z, s0.w, s1.x, s1.y, s1.z, s1.w,
                   s2.x, s2.y, s2.z, s2.w, s3.x, s3.y, s3.z, s3.w};
    unsigned hi[16], lo[16];
#pragma unroll
    for (int j = 0; j < 12; j++) split2(v[2 * j], v[2 * j + 1], hi[j], lo[j]);
#pragma unroll
    for (int j = 12; j < 16; j++) { hi[j] = 0u; lo[j] = 0u; }
#pragma unroll
    for (int j = 0; j < 4; j++) {
        *(uint4*)(Ah + pl * ASTRB + 512 + 16 * j) =
            make_uint4(hi[4 * j], hi[4 * j + 1], hi[4 * j + 2], hi[4 * j + 3]);
        *(uint4*)(Al + pl * ASTRB + 512 + 16 * j) =
            make_uint4(lo[4 * j], lo[4 * j + 1], lo[4 * j + 2], lo[4 * j + 3]);
    }
}

// ---------------- kernel 2: persistent warp-specialized gather || HMMA GEMM ----------------
__global__ __launch_bounds__(THREADS, 1)
void fused_kernel(const float* __restrict__ node_embs,
                  const int*   __restrict__ path_nodes,
                  const int*   __restrict__ path_lens,
                  const float* __restrict__ edge_feats,
                  const float* __restrict__ scalar_feats,
                  const float* __restrict__ W2,
                  const float* __restrict__ b2,
                  float*       __restrict__ out) {
    extern __shared__ __align__(16) char smc[];
    float* cs  = (float*)(smc + OFF_CS);
    float* w2s = (float*)(smc + OFF_W2);
    float* qp  = (float*)(smc + OFF_QP);
    int*   tick = (int*)(smc + OFF_TK);

    int t = threadIdx.x;
    int w = t >> 5, lane = t & 31;
    bool isP = (w >= 16);          // producer warps 16..23
    uint32_t sb = smem_u32(smc);

    const uint4* gBh4 = (const uint4*)g_Bh;
    const uint4* gBl4 = (const uint4*)g_Bl;

    // ---- prologue ----
    int cur = blockIdx.x;
    if (isP) {
        int pw = w - 16;
        char* Ah = smc; char* Al = smc + AHL;
#pragma unroll 1
        for (int pi = 0; pi < 8; pi++)
            gather_path(Ah, Al, node_embs, path_nodes, path_lens,
                        cur * MTILE + 8 * pw + pi, 8 * pw + pi, lane);
        if (t - 512 < MTILE)
            feat_rows(Ah, Al, edge_feats, scalar_feats, cur * MTILE + (t - 512), t - 512);
        if (t == 512) tick[0] = atomicAdd(&g_ticket, 1);
    } else {
        if (t < 256) {
            float cv = 0.f;
#pragma unroll
            for (int b = 0; b < 8; b++) cv += g_cpart[b][t];
            cs[t]  = cv;
            w2s[t] = W2[t];
        }
        // async-stage B chunk 0 into buf 0
        uint32_t dst = sb + OFF_B + (uint32_t)(t >> 5) * BSTRB + (uint32_t)(t & 31) * 16;
        cpa16(dst,        gBh4 + t);
        cpa16(dst + BSPL, gBl4 + t);
        CPA_COMMIT;
    }
    __syncthreads();

    // consumer GEMM mapping: 16 warps -> warp tile 16 rows x 64 cols
    int wr = w & 3, wc = (w >> 2) & 3;
    uint32_t a_off = (uint32_t)(wr * 16 + (lane & 15)) * ASTRB + ((lane >> 4) << 4);
    int bk = (lane & 7) + ((lane >> 4) << 3);
    int bn = wc * 64 + (((lane >> 3) & 1) << 3);
    uint32_t b_base = sb + OFF_B + (uint32_t)bk * BSTRB + (uint32_t)bn * 2;
    uint32_t b_dst  = sb + OFF_B + (uint32_t)(t >> 5) * BSTRB + (uint32_t)(t & 31) * 16;

    int buf = 0, it = 0;
    while (true) {
        int nxt = tick[it & 1];

        if (isP) {
            // ---- producer: gather tile nxt into the other A buffer ----
            if (nxt < NT) {
                int pw = w - 16;
                char* Ah = smc + (buf ^ 1) * ABUF;
                char* Al = Ah + AHL;
#pragma unroll 1
                for (int pi = 0; pi < 8; pi++)
                    gather_path(Ah, Al, node_embs, path_nodes, path_lens,
                                nxt * MTILE + 8 * pw + pi, 8 * pw + pi, lane);
                if (t - 512 < MTILE)
                    feat_rows(Ah, Al, edge_feats, scalar_feats,
                              nxt * MTILE + (t - 512), t - 512);
            }
            if (t == 512) tick[(it + 1) & 1] = (nxt < NT) ? atomicAdd(&g_ticket, 1) : NT;
        } else {
            // ---- consumer: GEMM tile cur from A[buf] ----
            uint32_t a_hi = sb + (uint32_t)buf * ABUF + a_off;
            uint32_t a_lo = a_hi + AHL;

            float d[8][4];
#pragma unroll
            for (int j = 0; j < 8; j++)
#pragma unroll
                for (int q = 0; q < 4; q++) d[j][q] = 0.f;

#pragma unroll 1
            for (int s = 0; s < NKS; s++) {
                BARC();             // all consumers done reading buf (s^1) from chunk s-1
                {                   // prefetch chunk s+1 (cyclic -> chunk 0 of next tile)
                    int c = s + 1 == NKS ? 0 : s + 1;
                    uint32_t dst = b_dst + (uint32_t)((s + 1) & 1) * BBUF;
                    cpa16(dst,        gBh4 + c * 512 + t);
                    cpa16(dst + BSPL, gBl4 + c * 512 + t);
                    CPA_COMMIT;
                }
                CPA_WAIT1;          // chunk s's copy (issued a full chunk ago) is done

                unsigned ah[4], al[4];
                ldsm4(ah, a_hi + s * 32);
                ldsm4(al, a_lo + s * 32);
                uint32_t bb = b_base + (uint32_t)(s & 1) * BBUF;
#pragma unroll
                for (int pr = 0; pr < 4; pr++) {
                    unsigned bh[4], bl[4];
                    ldsm4t(bh, bb + pr * 32);
                    ldsm4t(bl, bb + BSPL + pr * 32);
                    int n0 = pr * 2, n1 = n0 + 1;
                    mma_bf16(d[n0], ah, bh[0], bh[2]);
                    mma_bf16(d[n1], ah, bh[1], bh[3]);
                    mma_bf16(d[n0], ah, bl[0], bl[2]);
                    mma_bf16(d[n1], ah, bl[1], bl[3]);
                    mma_bf16(d[n0], al, bh[0], bh[2]);
                    mma_bf16(d[n1], al, bh[1], bh[3]);
                }
            }

            // ---- epilogue: +c, relu, dot(W2) partials ----
            int slot = (wc << 2) | (lane & 3);
            float qa = 0.f, qb = 0.f;
#pragma unroll
            for (int nt = 0; nt < 8; nt++) {
                int jg = wc * 64 + nt * 8 + 2 * (lane & 3);
                float c0 = cs[jg], c1 = cs[jg + 1];
                float w0 = w2s[jg], w1 = w2s[jg + 1];
                qa = fmaf(fmaxf(d[nt][0] + c0, 0.f), w0, qa);
                qa = fmaf(fmaxf(d[nt][1] + c1, 0.f), w1, qa);
                qb = fmaf(fmaxf(d[nt][2] + c0, 0.f), w0, qb);
                qb = fmaf(fmaxf(d[nt][3] + c1, 0.f), w1, qb);
            }
            int r = wr * 16 + (lane >> 2);
            qp[r * 17 + slot]       = qa;
            qp[(r + 8) * 17 + slot] = qb;
            BARC();
            if (t < MTILE) {
                int p = cur * MTILE + t;
                float sv = b2[0];
#pragma unroll
                for (int j = 0; j < 16; j++) sv += qp[t * 17 + j];
                out[p] = (path_lens[p] > 0) ? sv : 0.f;
            }
        }

        __syncthreads();        // tile rendezvous: A buffers swap
        if (nxt >= NT) break;
        cur = nxt; buf ^= 1; it++;
    }
}

// ---------------- launch ----------------
extern "C" void kernel_launch(void* const* d_in, const int* in_sizes, int n_in,
                              void* d_out, int out_size) {
    const float* node_embs    = (const float*)d_in[0];
    const int*   path_nodes   = (const int*)  d_in[1];
    const int*   path_lens    = (const int*)  d_in[2];
    const float* edge_feats   = (const float*)d_in[3];
    const float* scalar_feats = (const float*)d_in[4];
    const float* W1           = (const float*)d_in[5];
    const float* b1           = (const float*)d_in[6];
    const float* W2           = (const float*)d_in[7];
    const float* b2           = (const float*)d_in[8];
    const int*   src_idx      = (const int*)  d_in[9];
    const int*   dst_idx      = (const int*)  d_in[10];
    float* out = (float*)d_out;

    cudaFuncSetAttribute(fused_kernel,
                         cudaFuncAttributeMaxDynamicSharedMemorySize, SMEM_BYTES);

    prep_kernel<<<NKS + 8, H>>>(W1, node_embs, b1, src_idx, dst_idx);
    fused_kernel<<<GRID, THREADS, SMEM_BYTES>>>(
        node_embs, path_nodes, path_lens, edge_feats, scalar_feats, W2, b2, out);
}

// round 16
// speedup vs baseline: 1.6313x; 1.6313x over previous
#include <cuda_runtime.h>
#include <cuda_fp16.h>
#include <cstdint>

#define H 256
#define P_PATHS 32768
#define LMAX 16
#define NKS 18                 // k-steps of 16 (K = 288)
#define MTILE 64               // paths per tile
#define NT (P_PATHS / MTILE)   // 512 tiles
#define THREADS 512

// ---- dynamic smem byte offsets ----
#define ASTRB 592              // A row stride bytes (odd 16B segs -> conflict-free ldsm)
#define BSTRB 528
#define BCH   8448             // one B chunk buffer (16 k-rows x 528)
#define OFF_B  37888           // after A plane (64*592)
#define OFF_CS 63232           // 37888 + 3*8448
#define OFF_W2 64256
#define OFF_QP 65280           // float[64][17]
#define SMEM_BYTES 69632       // x2 CTAs = 139264 <= 228KB/SM

// ---------------- persistent scratch ----------------
__device__ __align__(128) unsigned g_Bf[NKS * 2048];   // [chunk][k(16)][n2(128)] fp16x2
__device__ __align__(128) float g_cpart[8][H];

// ---------------- helpers ----------------
__device__ __forceinline__ uint32_t smem_u32(const void* p) {
    uint32_t a;
    asm("{ .reg .u64 t; cvta.to.shared.u64 t, %1; cvt.u32.u64 %0, t; }" : "=r"(a) : "l"(p));
    return a;
}
__device__ __forceinline__ unsigned pk2h(float lo, float hi) {
    __half2 h = __floats2half2_rn(lo, hi);     // .x = lo (low bits), .y = hi
    return *reinterpret_cast<unsigned*>(&h);
}
__device__ __forceinline__ void ldsm4(unsigned* r, uint32_t a) {
    asm volatile("ldmatrix.sync.aligned.m8n8.x4.shared.b16 {%0,%1,%2,%3}, [%4];"
                 : "=r"(r[0]), "=r"(r[1]), "=r"(r[2]), "=r"(r[3]) : "r"(a));
}
__device__ __forceinline__ void ldsm4t(unsigned* r, uint32_t a) {
    asm volatile("ldmatrix.sync.aligned.m8n8.x4.trans.shared.b16 {%0,%1,%2,%3}, [%4];"
                 : "=r"(r[0]), "=r"(r[1]), "=r"(r[2]), "=r"(r[3]) : "r"(a));
}
__device__ __forceinline__ void mma_f16(float* d, const unsigned* a, unsigned b0, unsigned b1) {
    asm volatile("mma.sync.aligned.m16n8k16.row.col.f32.f16.f16.f32 "
                 "{%0,%1,%2,%3}, {%4,%5,%6,%7}, {%8,%9}, {%0,%1,%2,%3};"
                 : "+f"(d[0]), "+f"(d[1]), "+f"(d[2]), "+f"(d[3])
                 : "r"(a[0]), "r"(a[1]), "r"(a[2]), "r"(a[3]), "r"(b0), "r"(b1));
}
__device__ __forceinline__ void cpa16(uint32_t dst, const void* src) {
    asm volatile("cp.async.cg.shared.global [%0], [%1], 16;" :: "r"(dst), "l"(src) : "memory");
}
#define CPA_COMMIT asm volatile("cp.async.commit_group;" ::: "memory")
#define CPA_WAIT0  asm volatile("cp.async.wait_group 0;"  ::: "memory")
#define CPA_WAIT1  asm volatile("cp.async.wait_group 1;"  ::: "memory")
#define CPA_WAIT2  asm volatile("cp.async.wait_group 2;"  ::: "memory")

// fused-k -> W1 row: [src 0:256 | dst 256:512 | emb 512:768 | edge 768:776 | scalar 776:792]
__device__ __forceinline__ float wfused(const float* W1, int kg, int j) {
    if (kg < 256) return W1[(512 + kg) * H + j];
    if (kg < 264) return W1[(768 + (kg - 256)) * H + j];
    if (kg < 280) return W1[(776 + (kg - 264)) * H + j];
    return 0.f;
}

// ---------------- kernel 1: prep (pack fp16 W chunks, c partials) ----------------
__global__ void prep_kernel(const float* __restrict__ W1,
                            const float* __restrict__ node_embs,
                            const float* __restrict__ b1,
                            const int* __restrict__ src_idx,
                            const int* __restrict__ dst_idx) {
    int bid = blockIdx.x;
    int t = threadIdx.x;
    if (bid < NKS) {
        int c = bid;
        int kk = t >> 7;
        int n2 = t & 127;
#pragma unroll
        for (int i = 0; i < 8; i++) {
            int k = i * 2 + kk;
            float v0 = wfused(W1, c * 16 + k, 2 * n2);
            float v1 = wfused(W1, c * 16 + k, 2 * n2 + 1);
            g_Bf[c * 2048 + k * 128 + n2] = pk2h(v0, v1);
        }
    } else {
        int b = bid - NKS;
        const float* s = node_embs + (long)(*src_idx) * H;
        const float* d = node_embs + (long)(*dst_idx) * H;
        float acc = (b == 0) ? b1[t] : 0.f;
        int k0 = b * 32;
#pragma unroll 8
        for (int k = k0; k < k0 + 32; k++) {
            acc = fmaf(s[k], W1[k * H + t], acc);
            acc = fmaf(d[k], W1[(256 + k) * H + t], acc);
        }
        g_cpart[b][t] = acc;
    }
}

// ---------------- gather: one path mean -> fp16 row of A ----------------
__device__ __forceinline__ void gather_path(char* __restrict__ Af,
                                            const float* __restrict__ node_embs,
                                            const int* __restrict__ path_nodes,
                                            const int* __restrict__ path_lens,
                                            int p, int pl, int lane) {
    int len = path_lens[p];
    const int4* nb = (const int4*)(path_nodes + (size_t)p * LMAX);
    int4 q0 = nb[0], q1 = nb[1], q2 = nb[2], q3 = nb[3];
    int ids[16] = {q0.x, q0.y, q0.z, q0.w, q1.x, q1.y, q1.z, q1.w,
                   q2.x, q2.y, q2.z, q2.w, q3.x, q3.y, q3.z, q3.w};
    float4 a0 = make_float4(0.f, 0.f, 0.f, 0.f);
    float4 a1 = make_float4(0.f, 0.f, 0.f, 0.f);
#pragma unroll
    for (int l = 0; l < LMAX; l++) {
        if (l < len) {
            const float4* r = (const float4*)(node_embs + (size_t)ids[l] * H);
            float4 v0 = r[lane];          // k = 4*lane ..
            float4 v1 = r[32 + lane];     // k = 128 + 4*lane ..
            a0.x += v0.x; a0.y += v0.y; a0.z += v0.z; a0.w += v0.w;
            a1.x += v1.x; a1.y += v1.y; a1.z += v1.z; a1.w += v1.w;
        }
    }
    float inv = 1.f / (float)max(len, 1);
    *(uint2*)(Af + pl * ASTRB + lane * 8) =
        make_uint2(pk2h(a0.x * inv, a0.y * inv), pk2h(a0.z * inv, a0.w * inv));
    *(uint2*)(Af + pl * ASTRB + 256 + lane * 8) =
        make_uint2(pk2h(a1.x * inv, a1.y * inv), pk2h(a1.z * inv, a1.w * inv));
}

__device__ __forceinline__ void feat_rows(char* __restrict__ Af,
                                          const float* __restrict__ edge_feats,
                                          const float* __restrict__ scalar_feats,
                                          int p, int pl) {
    const float4* ef = (const float4*)(edge_feats + (size_t)p * 8);
    float4 e0 = ef[0], e1 = ef[1];
    const float4* sf = (const float4*)(scalar_feats + (size_t)p * 16);
    float4 s0 = sf[0], s1 = sf[1], s2 = sf[2], s3 = sf[3];
    float v[24] = {e0.x, e0.y, e0.z, e0.w, e1.x, e1.y, e1.z, e1.w,
                   s0.x, s0.y, s0.z, s0.w, s1.x, s1.y, s1.z, s1.w,
                   s2.x, s2.y, s2.z, s2.w, s3.x, s3.y, s3.z, s3.w};
    unsigned h[16];
#pragma unroll
    for (int j = 0; j < 12; j++) h[j] = pk2h(v[2 * j], v[2 * j + 1]);
#pragma unroll
    for (int j = 12; j < 16; j++) h[j] = 0u;
#pragma unroll
    for (int j = 0; j < 4; j++) {
        *(uint4*)(Af + pl * ASTRB + 512 + 16 * j) =
            make_uint4(h[4 * j], h[4 * j + 1], h[4 * j + 2], h[4 * j + 3]);
    }
}

// ---------------- kernel 2: fused gather + fp16 HMMA GEMM, 512 thr, 2 CTAs/SM ----------------
__global__ __launch_bounds__(THREADS, 2)
void fused_kernel(const float* __restrict__ node_embs,
                  const int*   __restrict__ path_nodes,
                  const int*   __restrict__ path_lens,
                  const float* __restrict__ edge_feats,
                  const float* __restrict__ scalar_feats,
                  const float* __restrict__ W2,
                  const float* __restrict__ b2,
                  float*       __restrict__ out) {
    extern __shared__ __align__(16) char smc[];
    char*  Af  = smc;                       // fp16 A plane [64][296]
    float* cs  = (float*)(smc + OFF_CS);
    float* w2s = (float*)(smc + OFF_W2);
    float* qp  = (float*)(smc + OFF_QP);

    int t = threadIdx.x;
    int w = t >> 5, lane = t & 31;
    int p0 = blockIdx.x * MTILE;
    uint32_t sb = smem_u32(smc);

    const uint4* gBf4 = (const uint4*)g_Bf;
    uint32_t b_dst = sb + OFF_B + (uint32_t)(t >> 5) * BSTRB + (uint32_t)(t & 31) * 16;

    // ---- async-stage B chunks 0..2 (ride under the gather), one group each ----
    cpa16(b_dst + 0 * BCH, gBf4 + 0 * 512 + t); CPA_COMMIT;
    cpa16(b_dst + 1 * BCH, gBf4 + 1 * 512 + t); CPA_COMMIT;
    cpa16(b_dst + 2 * BCH, gBf4 + 2 * 512 + t); CPA_COMMIT;

    // constants
    if (t < 256) {
        float cv = 0.f;
#pragma unroll
        for (int b = 0; b < 8; b++) cv += g_cpart[b][t];
        cs[t]  = cv;
        w2s[t] = W2[t];
    }

    // ---- phase 1: gather 64 paths (4 per warp) ----
#pragma unroll 1
    for (int pi = 0; pi < 4; pi++)
        gather_path(Af, node_embs, path_nodes, path_lens,
                    p0 + 4 * w + pi, 4 * w + pi, lane);
    if (t < MTILE)
        feat_rows(Af, edge_feats, scalar_feats, p0 + t, t);

    CPA_WAIT2;           // chunk 0 landed
    __syncthreads();     // A + B0 + constants visible

    // ---- phase 2: GEMM. 16 warps, warp tile 16 rows x 64 cols ----
    int wr = w & 3, wc = w >> 2;
    uint32_t a_base = sb + (uint32_t)(wr * 16 + (lane & 15)) * ASTRB + ((lane >> 4) << 4);
    int bk = (lane & 7) + ((lane >> 4) << 3);
    int bn = wc * 64 + (((lane >> 3) & 1) << 3);
    uint32_t bko = (uint32_t)bk * BSTRB + (uint32_t)bn * 2;

    float d[8][4];
#pragma unroll
    for (int j = 0; j < 8; j++)
#pragma unroll
        for (int q = 0; q < 4; q++) d[j][q] = 0.f;

    int bf = 0;          // s % 3
#pragma unroll 1
    for (int s = 0; s < NKS; s++) {
        uint32_t bb = sb + OFF_B + (uint32_t)bf * BCH + bko;
        unsigned a[4];
        ldsm4(a, a_base + s * 32);
#pragma unroll
        for (int pr = 0; pr < 4; pr++) {
            unsigned b[4];
            ldsm4t(b, bb + pr * 32);
            mma_f16(d[2 * pr],     a, b[0], b[2]);
            mma_f16(d[2 * pr + 1], a, b[1], b[3]);
        }
        if (s < NKS - 1) {
            if (s == NKS - 2) { CPA_WAIT0; } else { CPA_WAIT1; }   // chunk s+1 landed
            __syncthreads();                                        // + all done reading buf bf
            int c = s + 3;
            if (c < NKS) {
                cpa16(b_dst + (uint32_t)bf * BCH, gBf4 + c * 512 + t);
                CPA_COMMIT;
            }
        }
        bf = (bf == 2) ? 0 : bf + 1;
    }

    // ---- epilogue: +c, relu, dot(W2) partials ----
    {
        int slot = (wc << 2) | (lane & 3);
        float qa = 0.f, qb = 0.f;
#pragma unroll
        for (int nt = 0; nt < 8; nt++) {
            int jg = wc * 64 + nt * 8 + 2 * (lane & 3);
            float c0 = cs[jg], c1 = cs[jg + 1];
            float w0 = w2s[jg], w1 = w2s[jg + 1];
            qa = fmaf(fmaxf(d[nt][0] + c0, 0.f), w0, qa);
            qa = fmaf(fmaxf(d[nt][1] + c1, 0.f), w1, qa);
            qb = fmaf(fmaxf(d[nt][2] + c0, 0.f), w0, qb);
            qb = fmaf(fmaxf(d[nt][3] + c1, 0.f), w1, qb);
        }
        int r = wr * 16 + (lane >> 2);
        qp[r * 17 + slot]       = qa;
        qp[(r + 8) * 17 + slot] = qb;
    }
    __syncthreads();

    if (t < MTILE) {
        int p = p0 + t;
        float sv = b2[0];
#pragma unroll
        for (int j = 0; j < 16; j++) sv += qp[t * 17 + j];
        out[p] = (path_lens[p] > 0) ? sv : 0.f;
    }
}

// ---------------- launch ----------------
extern "C" void kernel_launch(void* const* d_in, const int* in_sizes, int n_in,
                              void* d_out, int out_size) {
    const float* node_embs    = (const float*)d_in[0];
    const int*   path_nodes   = (const int*)  d_in[1];
    const int*   path_lens    = (const int*)  d_in[2];
    const float* edge_feats   = (const float*)d_in[3];
    const float* scalar_feats = (const float*)d_in[4];
    const float* W1           = (const float*)d_in[5];
    const float* b1           = (const float*)d_in[6];
    const float* W2           = (const float*)d_in[7];
    const float* b2           = (const float*)d_in[8];
    const int*   src_idx      = (const int*)  d_in[9];
    const int*   dst_idx      = (const int*)  d_in[10];
    float* out = (float*)d_out;

    cudaFuncSetAttribute(fused_kernel,
                         cudaFuncAttributeMaxDynamicSharedMemorySize, SMEM_BYTES);

    prep_kernel<<<NKS + 8, H>>>(W1, node_embs, b1, src_idx, dst_idx);
    fused_kernel<<<NT, THREADS, SMEM_BYTES>>>(
        node_embs, path_nodes, path_lens, edge_feats, scalar_feats, W2, b2, out);
}